// round 14
// baseline (speedup 1.0000x reference)
#include <cuda_runtime.h>
#include <cuda.h>
#include <cuda_fp16.h>
#include <cstdint>

// Problem constants
#define BSZ   16384
#define SE    2048
#define SO    2048
#define H1    1024
#define NSTEP 10

// GEMM tiling (2 CTAs/SM)
#define BM 128
#define BN 128
#define BK 64
#define STG 3
#define ATILE 16384                     // 128 rows x 128 B
#define STAGE_BYTES (2 * ATILE)         // A + B
#define SMEM_ALLOC (STG * STAGE_BYTES + 1024)   // 99328 B -> 2 CTAs/SM

// prep grid layout: [csum2 2048][csum1 64][prepA 32768][prepW 4096]
#define PREP_CS2 2048
#define PREP_CS1 64
#define PREP_A   32768
#define PREP_W   4096
#define PREP_GRID (PREP_CS2 + PREP_CS1 + PREP_A + PREP_W)

// ---------------------------------------------------------------------------
// Scratch (device globals; no allocation allowed)
// ---------------------------------------------------------------------------
__device__ __align__(1024) __half g_A1[(size_t)BSZ * SE];   // rho(s_even)-0.5
__device__ __align__(1024) __half g_A2[(size_t)BSZ * SE];   // rho(s_odd)-0.5
__device__ __align__(1024) __half g_W1[(size_t)SO * SE];    // W1[n][k] = W[k][n]
__device__ __align__(1024) __half g_W2[(size_t)SE * SO];    // W2[n][k] = W[n][k]
__device__ float g_csum1[SO];
__device__ float g_csum2[SE];

// ---------------------------------------------------------------------------
// Helpers
// ---------------------------------------------------------------------------
__device__ __forceinline__ float ex2f(float x) {
    float y; asm("ex2.approx.f32 %0, %1;" : "=f"(y) : "f"(x)); return y;
}
__device__ __forceinline__ float rcpf(float x) {
    float y; asm("rcp.approx.f32 %0, %1;" : "=f"(y) : "f"(x)); return y;
}
__device__ __forceinline__ float tanh_ap(float x) {
    float y; asm("tanh.approx.f32 %0, %1;" : "=f"(y) : "f"(x)); return y;
}
#define RHO_A (-5.770780163555852f)
#define RHO_B ( 2.885390081777926f)
__device__ __forceinline__ float rho_f(float x) {
    float q = ex2f(fmaf(RHO_A, x, RHO_B));
    return rcpf(1.0f + q);
}
__device__ __forceinline__ uint32_t cvta_smem(const void* p) {
    uint32_t a;
    asm("{ .reg .u64 t; cvta.to.shared.u64 t, %1; cvt.u32.u64 %0, t; }" : "=r"(a) : "l"(p));
    return a;
}
__device__ __forceinline__ void mbar_init(uint32_t a, uint32_t cnt) {
    asm volatile("mbarrier.init.shared.b64 [%0], %1;" :: "r"(a), "r"(cnt) : "memory");
}
__device__ __forceinline__ void mbar_expect_tx(uint32_t a, uint32_t b) {
    asm volatile("mbarrier.arrive.expect_tx.shared.b64 _, [%0], %1;" :: "r"(a), "r"(b) : "memory");
}
__device__ __forceinline__ void mbar_arrive(uint32_t a) {
    asm volatile("mbarrier.arrive.release.cta.shared::cta.b64 _, [%0];" :: "r"(a) : "memory");
}
__device__ __forceinline__ void mbar_wait(uint32_t a, uint32_t ph) {
    asm volatile(
        "{\n\t.reg .pred P;\n"
        "LW%=:\n\t"
        "mbarrier.try_wait.parity.acquire.cta.shared::cta.b64 P, [%0], %1, 0x989680;\n\t"
        "@P bra LD%=;\n\t"
        "bra LW%=;\n"
        "LD%=:\n\t}"
        :: "r"(a), "r"(ph) : "memory");
}
__device__ __forceinline__ void tma2d(uint32_t dst, const CUtensorMap* tm, int x, int y, uint32_t mbar) {
    asm volatile(
        "cp.async.bulk.tensor.2d.shared::cta.global.tile.mbarrier::complete_tx::bytes "
        "[%0], [%1, {%2, %3}], [%4];"
        :: "r"(dst), "l"(tm), "r"(x), "r"(y), "r"(mbar) : "memory");
}
__device__ __forceinline__ void mma16816(float d[4], const uint32_t a[4], uint32_t b0, uint32_t b1) {
    asm volatile(
        "mma.sync.aligned.m16n8k16.row.col.f32.f16.f16.f32 "
        "{%0,%1,%2,%3}, {%4,%5,%6,%7}, {%8,%9}, {%0,%1,%2,%3};\n"
        : "+f"(d[0]), "+f"(d[1]), "+f"(d[2]), "+f"(d[3])
        : "r"(a[0]), "r"(a[1]), "r"(a[2]), "r"(a[3]), "r"(b0), "r"(b1));
}
__device__ __forceinline__ void ldsm4(uint32_t f[4], uint32_t addr) {
    asm volatile("ldmatrix.sync.aligned.m8n8.x4.shared.b16 {%0,%1,%2,%3}, [%4];\n"
                 : "=r"(f[0]), "=r"(f[1]), "=r"(f[2]), "=r"(f[3]) : "r"(addr));
}
__device__ __forceinline__ void prefetchL2(const void* p) {
    asm volatile("prefetch.global.L2 [%0];" :: "l"(p));
}

// ---------------------------------------------------------------------------
// Merged prep kernel — reductions FIRST, streaming work behind them
// ---------------------------------------------------------------------------
__global__ void prep_all(const float* __restrict__ s, const float* __restrict__ W,
                         const float* __restrict__ b_even, const float* __restrict__ b_odd) {
    const int b = blockIdx.x;
    const int tid = threadIdx.x;
    if (b < PREP_CS2) {
        // csum2[n] = 0.5*rowsum(W[n,:]) + b_even[n]
        __shared__ float red[256];
        int n = b;
        float p = 0.f;
        for (int k = tid; k < SO; k += 256) p += W[(size_t)n * SO + k];
        red[tid] = p;
        __syncthreads();
        for (int st = 128; st > 0; st >>= 1) {
            if (tid < st) red[tid] += red[tid + st];
            __syncthreads();
        }
        if (tid == 0) g_csum2[n] = 0.5f * red[0] + b_even[n];
    } else if (b < PREP_CS2 + PREP_CS1) {
        // csum1[c] = 0.5*colsum(W[:,c]) + b_odd[c]; 64 blocks x (32 cols, 8 k-slices)
        __shared__ float red[8][32];
        int i  = b - PREP_CS2;
        int c  = i * 32 + (tid & 31);
        int ks = tid >> 5;               // 0..7
        float p = 0.f;
        for (int k = ks * 256; k < ks * 256 + 256; k++) p += W[(size_t)k * SO + c];
        red[ks][tid & 31] = p;
        __syncthreads();
        if (tid < 32) {
            float sum = red[0][tid];
#pragma unroll
            for (int j = 1; j < 8; j++) sum += red[j][tid];
            g_csum1[c] = 0.5f * sum + b_odd[c];
        }
    } else if (b < PREP_CS2 + PREP_CS1 + PREP_A) {
        // prepA: rho(s_even)-0.5 -> g_A1 (fp16)
        int id = (b - PREP_CS2 - PREP_CS1) * 256 + tid;
        int m  = id >> 9;
        int kc = id & 511;
        float4 x = reinterpret_cast<const float4*>(s + (size_t)m * (SE + SO))[kc];
        float r0 = rho_f(x.x) - 0.5f;
        float r1 = rho_f(x.y) - 0.5f;
        float r2 = rho_f(x.z) - 0.5f;
        float r3 = rho_f(x.w) - 0.5f;
        __half2* dst = reinterpret_cast<__half2*>(g_A1 + (size_t)m * SE);
        dst[kc * 2 + 0] = __floats2half2_rn(r0, r1);
        dst[kc * 2 + 1] = __floats2half2_rn(r2, r3);
    } else {
        // prepW: W -> g_W2 (fp16) and transpose -> g_W1
        __shared__ float tile[32][33];
        int i  = b - PREP_CS2 - PREP_CS1 - PREP_A;
        int bx = (i & 63) * 32;   // n
        int by = (i >> 6) * 32;   // k
        int tx = tid & 31, ty = tid >> 5;   // 32 x 8
#pragma unroll
        for (int j = 0; j < 32; j += 8) {
            int r = by + ty + j, c = bx + tx;
            float w = W[(size_t)r * SO + c];
            g_W2[(size_t)r * SO + c] = __float2half(w);
            tile[ty + j][tx] = w;
        }
        __syncthreads();
#pragma unroll
        for (int j = 0; j < 32; j += 8) {
            float w = tile[tx][ty + j];
            g_W1[(size_t)(bx + ty + j) * SE + by + tx] = __float2half(w);
        }
    }
}

// ---------------------------------------------------------------------------
// Fused GEMM (TMA + HMMA, deferred-refill producer) + all-tanh iteration
// ---------------------------------------------------------------------------
template <int PHASE>
__global__ void __launch_bounds__(256, 2)
gemm_fused(const __grid_constant__ CUtensorMap tmA,
           const __grid_constant__ CUtensorMap tmB,
           const float* __restrict__ s_in, const float* __restrict__ Ux,
           float* __restrict__ out) {
    extern __shared__ char smem[];
    const uint32_t s0 = cvta_smem(smem);
    const float* csum_g = (PHASE == 1) ? g_csum1 : g_csum2;

    const int tid  = threadIdx.x;
    const int warp = tid >> 5, lane = tid & 31;
    const int wm = warp & 1, wn = warp >> 1;     // 2 warps along M, 4 along N
    const int m0 = blockIdx.y * BM;

    // heavy/light alternation by row parity: co-resident CTAs get mixed
    // durations so epilogue MUFU bursts overlap the other CTA's mainloop.
    const int x = blockIdx.x, y = blockIdx.y;
    int xr;
    if (PHASE == 1) xr = ((y & 1) == 0) ? ((x < 8) ? x + 8 : x - 8) : x;
    else            xr = ((y & 1) == 0) ? x : ((x + 8) & 15);
    const int n0 = xr * BN;

    // block-sparse K range
    int k_lo, k_hi;
    if (PHASE == 1) { k_lo = 0; k_hi = (n0 < H1) ? 1024 : 2048; }
    else            { k_lo = (n0 < H1) ? 0 : 1024; k_hi = 2048; }
    const int total = (k_hi - k_lo) >> 6;        // 16 or 32 k-tiles, >= STG

    const uint32_t fullb = s0;                   // STG x 8 B (TMA tx barriers)
    const uint32_t consb = s0 + 64;              // STG x 8 B (consumed, 8 warp arrivals)
    float* csm = reinterpret_cast<float*>(smem + 256);   // 128 floats in header
    const uint32_t tbase = s0 + 1024;

    if (tid == 0) {
#pragma unroll
        for (int i = 0; i < STG; i++) {
            mbar_init(fullb + 8 * i, 1);
            mbar_init(consb + 8 * i, 8);
        }
    }
    // csum has no GEMM dependency: stage it before the mainloop
    if (tid < BN) csm[tid] = csum_g[n0 + tid];
    __syncthreads();

    auto issue_stage = [&](int st) {
        const int b = st % STG;
        const uint32_t mb = fullb + 8 * b;
        const int kt = k_lo + st * BK;
        const uint32_t d = tbase + b * STAGE_BYTES;
        mbar_expect_tx(mb, STAGE_BYTES);
        tma2d(d,         &tmA, kt, m0, mb);
        tma2d(d + ATILE, &tmB, kt, n0, mb);
    };

    if (tid == 0) {
#pragma unroll
        for (int st = 0; st < STG; st++) issue_stage(st);
    }

    // loop-invariant ldmatrix address components
    const uint32_t arow = wm * 64 + (lane & 15);
    const uint32_t abit = (lane >> 4);
    const uint32_t brow = wn * 32 + ((lane >> 4) << 3) + (lane & 7);
    const uint32_t bbit = ((lane >> 3) & 1);

    // epilogue addressing (also used for L2 prefetch during mainloop)
    const int g  = lane >> 2;
    const int col_off = (PHASE == 1) ? SO : 0;
    const bool tile_has_ux = (PHASE == 1) && (n0 < H1);

    float acc[4][4][4];
#pragma unroll
    for (int a = 0; a < 4; a++)
#pragma unroll
        for (int b = 0; b < 4; b++)
#pragma unroll
            for (int c = 0; c < 4; c++) acc[a][b][c] = 0.f;

    for (int st = 0; st < total; st++) {
        const int buf = st % STG;
        const uint32_t ph = (st / STG) & 1;

        // deferred refill: previous tile's buffer, whose consumers had a full
        // extra tile to arrive -> near-zero wait for warp 0
        if (tid == 0 && st > 0 && (st - 1) + STG < total) {
            const int pb = (st - 1) % STG;
            mbar_wait(consb + 8 * pb, ((st - 1) / STG) & 1);
            issue_stage(st - 1 + STG);
        }

        // warm L2 for the epilogue's s/Ux rows while tensor pipe is busy
        if (st == total - 3) {
#pragma unroll
            for (int mi = 0; mi < 4; mi++)
#pragma unroll
                for (int rr = 0; rr < 2; rr++) {
                    const int row = m0 + wm * 64 + mi * 16 + g + rr * 8;
                    const int cb  = n0 + wn * 32;
                    prefetchL2(s_in + (size_t)row * (SE + SO) + col_off + cb);
                    if (tile_has_ux) prefetchL2(Ux + (size_t)row * H1 + cb);
                }
        }

        mbar_wait(fullb + 8 * buf, ph);

        const uint32_t bufA = tbase + buf * STAGE_BYTES;
        const uint32_t bufB = bufA + ATILE;

        uint32_t af[2][4][4];
        uint32_t bf[2][2][4];

        auto ldfrags = [&](int ks, int slot) {
#pragma unroll
            for (int mi = 0; mi < 4; mi++) {
                uint32_t row = arow + mi * 16;
                uint32_t chunk = (ks * 2 + abit) ^ (row & 7);
                ldsm4(af[slot][mi], bufA + row * 128 + (chunk << 4));
            }
#pragma unroll
            for (int nj = 0; nj < 2; nj++) {
                uint32_t row = brow + nj * 16;
                uint32_t chunk = (ks * 2 + bbit) ^ (row & 7);
                ldsm4(bf[slot][nj], bufB + row * 128 + (chunk << 4));
            }
        };

        ldfrags(0, 0);
#pragma unroll
        for (int ks = 0; ks < 4; ks++) {
            const int cur = ks & 1;
            if (ks < 3) ldfrags(ks + 1, cur ^ 1);
#pragma unroll
            for (int mi = 0; mi < 4; mi++)
#pragma unroll
                for (int ni = 0; ni < 4; ni++)
                    mma16816(acc[mi][ni], af[cur][mi],
                             bf[cur][ni >> 1][(ni & 1) * 2],
                             bf[cur][ni >> 1][(ni & 1) * 2 + 1]);
        }

        // mark this buffer consumed (only needed if it will be refilled)
        if (lane == 0 && st + STG < total) mbar_arrive(consb + 8 * buf);
    }

    // ---------------- fused epilogue (all-tanh), per-warp immediate entry ----
    // No block sync needed: each warp consumes only its own acc + read-only csm.
    const int i2 = (lane & 3) * 2;

#pragma unroll
    for (int mi = 0; mi < 4; mi++) {
#pragma unroll
        for (int rr = 0; rr < 2; rr++) {
            const int row = m0 + wm * 64 + mi * 16 + g + rr * 8;
#pragma unroll
            for (int ni = 0; ni < 4; ni++) {
                const int lc  = wn * 32 + ni * 8 + i2;     // local col pair
                const int col = n0 + lc;
                float c0 = acc[mi][ni][rr * 2 + 0] + csm[lc + 0];
                float c1 = acc[mi][ni][rr * 2 + 1] + csm[lc + 1];
                if (tile_has_ux) {
                    float2 u = *reinterpret_cast<const float2*>(Ux + (size_t)row * H1 + col);
                    c0 += u.x; c1 += u.y;
                }
                float2 sv = *reinterpret_cast<const float2*>(
                    s_in + (size_t)row * (SE + SO) + col_off + col);
                const float h0 = 0.5f * c0, h1 = 0.5f * c1;
#pragma unroll
                for (int it = 0; it < NSTEP; it++) {
                    float t0 = tanh_ap(fmaf(2.0f, sv.x, -1.0f));
                    float t1 = tanh_ap(fmaf(2.0f, sv.y, -1.0f));
                    sv.x = fmaf(-h0 * t0, t0, fmaf(0.5f, sv.x, h0));
                    sv.y = fmaf(-h1 * t1, t1, fmaf(0.5f, sv.y, h1));
                }
                *reinterpret_cast<float2*>(out + (size_t)row * (SE + SO) + col_off + col) = sv;
                if (PHASE == 1) {
                    // rho(s)-0.5 = 0.5*tanh(2s-1)
                    float r0 = 0.5f * tanh_ap(fmaf(2.0f, sv.x, -1.0f));
                    float r1 = 0.5f * tanh_ap(fmaf(2.0f, sv.y, -1.0f));
                    *reinterpret_cast<__half2*>(g_A2 + (size_t)row * SE + col) =
                        __floats2half2_rn(r0, r1);
                }
            }
        }
    }
}

// ---------------------------------------------------------------------------
// Host: tensor-map encoding via driver entry point (no -lcuda needed)
// ---------------------------------------------------------------------------
typedef CUresult (*encode_fn_t)(CUtensorMap*, CUtensorMapDataType, cuuint32_t, void*,
                                const cuuint64_t*, const cuuint64_t*, const cuuint32_t*,
                                const cuuint32_t*, CUtensorMapInterleave, CUtensorMapSwizzle,
                                CUtensorMapL2promotion, CUtensorMapFloatOOBfill);

static void encode_tm(encode_fn_t enc, CUtensorMap* tm, void* base,
                      unsigned long long rows) {
    cuuint64_t gd[2] = {2048ull, rows};
    cuuint64_t gs[1] = {4096ull};          // row stride in bytes
    cuuint32_t box[2] = {64u, 128u};       // K box (128 B) x 128 rows
    cuuint32_t es[2] = {1u, 1u};
    enc(tm, CU_TENSOR_MAP_DATA_TYPE_FLOAT16, 2, base, gd, gs, box, es,
        CU_TENSOR_MAP_INTERLEAVE_NONE, CU_TENSOR_MAP_SWIZZLE_128B,
        CU_TENSOR_MAP_L2_PROMOTION_L2_128B, CU_TENSOR_MAP_FLOAT_OOB_FILL_NONE);
}

extern "C" void kernel_launch(void* const* d_in, const int* in_sizes, int n_in,
                              void* d_out, int out_size) {
    const float* Ux     = (const float*)d_in[0];
    const float* s      = (const float*)d_in[1];
    const float* W      = (const float*)d_in[2];
    const float* b_even = (const float*)d_in[3];
    const float* b_odd  = (const float*)d_in[4];
    float* out = (float*)d_out;

    encode_fn_t enc = nullptr;
    cudaDriverEntryPointQueryResult qr;
    cudaGetDriverEntryPoint("cuTensorMapEncodeTiled", (void**)&enc, cudaEnableDefault, &qr);

    void *pA1, *pA2, *pW1, *pW2;
    cudaGetSymbolAddress(&pA1, g_A1);
    cudaGetSymbolAddress(&pA2, g_A2);
    cudaGetSymbolAddress(&pW1, g_W1);
    cudaGetSymbolAddress(&pW2, g_W2);

    CUtensorMap tmA1, tmA2, tmW1, tmW2;
    encode_tm(enc, &tmA1, pA1, BSZ);
    encode_tm(enc, &tmA2, pA2, BSZ);
    encode_tm(enc, &tmW1, pW1, SO);
    encode_tm(enc, &tmW2, pW2, SE);

    cudaFuncSetAttribute(gemm_fused<1>, cudaFuncAttributeMaxDynamicSharedMemorySize, SMEM_ALLOC);
    cudaFuncSetAttribute(gemm_fused<2>, cudaFuncAttributeMaxDynamicSharedMemorySize, SMEM_ALLOC);

    prep_all<<<PREP_GRID, 256>>>(s, W, b_even, b_odd);

    dim3 grid(SO / BN, BSZ / BM);   // (16, 128)
    gemm_fused<1><<<grid, 256, SMEM_ALLOC>>>(tmA1, tmW1, s, Ux, out);
    gemm_fused<2><<<grid, 256, SMEM_ALLOC>>>(tmA2, tmW2, s, Ux, out);
}

// round 15
// speedup vs baseline: 1.0851x; 1.0851x over previous
#include <cuda_runtime.h>
#include <cuda.h>
#include <cuda_fp16.h>
#include <cstdint>

// Problem constants
#define BSZ   16384
#define SE    2048
#define SO    2048
#define H1    1024
#define NSTEP 10

// GEMM tiling (2 CTAs/SM)
#define BM 128
#define BN 128
#define BK 64
#define STG 3
#define ATILE 16384                     // 128 rows x 128 B
#define STAGE_BYTES (2 * ATILE)         // A + B
#define SMEM_ALLOC (STG * STAGE_BYTES + 1024)   // 99328 B -> 2 CTAs/SM

// prep grid layout: [csum2 2048][csum1 64][prepA 32768][prepW 4096]
#define PREP_CS2 2048
#define PREP_CS1 64
#define PREP_A   32768
#define PREP_W   4096
#define PREP_GRID (PREP_CS2 + PREP_CS1 + PREP_A + PREP_W)

// ---------------------------------------------------------------------------
// Scratch (device globals; no allocation allowed)
// ---------------------------------------------------------------------------
__device__ __align__(1024) __half g_A1[(size_t)BSZ * SE];   // rho(s_even)-0.5
__device__ __align__(1024) __half g_A2[(size_t)BSZ * SE];   // rho(s_odd)-0.5
__device__ __align__(1024) __half g_W1[(size_t)SO * SE];    // W1[n][k] = W[k][n]
__device__ __align__(1024) __half g_W2[(size_t)SE * SO];    // W2[n][k] = W[n][k]
__device__ float g_csum1[SO];
__device__ float g_csum2[SE];

// ---------------------------------------------------------------------------
// Helpers
// ---------------------------------------------------------------------------
__device__ __forceinline__ float ex2f(float x) {
    float y; asm("ex2.approx.f32 %0, %1;" : "=f"(y) : "f"(x)); return y;
}
__device__ __forceinline__ float rcpf(float x) {
    float y; asm("rcp.approx.f32 %0, %1;" : "=f"(y) : "f"(x)); return y;
}
__device__ __forceinline__ float tanh_ap(float x) {
    float y; asm("tanh.approx.f32 %0, %1;" : "=f"(y) : "f"(x)); return y;
}
#define RHO_A (-5.770780163555852f)
#define RHO_B ( 2.885390081777926f)
__device__ __forceinline__ float rho_f(float x) {
    float q = ex2f(fmaf(RHO_A, x, RHO_B));
    return rcpf(1.0f + q);
}
__device__ __forceinline__ uint32_t cvta_smem(const void* p) {
    uint32_t a;
    asm("{ .reg .u64 t; cvta.to.shared.u64 t, %1; cvt.u32.u64 %0, t; }" : "=r"(a) : "l"(p));
    return a;
}
__device__ __forceinline__ void mbar_init(uint32_t a, uint32_t cnt) {
    asm volatile("mbarrier.init.shared.b64 [%0], %1;" :: "r"(a), "r"(cnt) : "memory");
}
__device__ __forceinline__ void mbar_expect_tx(uint32_t a, uint32_t b) {
    asm volatile("mbarrier.arrive.expect_tx.shared.b64 _, [%0], %1;" :: "r"(a), "r"(b) : "memory");
}
__device__ __forceinline__ void mbar_arrive(uint32_t a) {
    asm volatile("mbarrier.arrive.release.cta.shared::cta.b64 _, [%0];" :: "r"(a) : "memory");
}
__device__ __forceinline__ void mbar_wait(uint32_t a, uint32_t ph) {
    asm volatile(
        "{\n\t.reg .pred P;\n"
        "LW%=:\n\t"
        "mbarrier.try_wait.parity.acquire.cta.shared::cta.b64 P, [%0], %1, 0x989680;\n\t"
        "@P bra LD%=;\n\t"
        "bra LW%=;\n"
        "LD%=:\n\t}"
        :: "r"(a), "r"(ph) : "memory");
}
__device__ __forceinline__ void tma2d(uint32_t dst, const CUtensorMap* tm, int x, int y, uint32_t mbar) {
    asm volatile(
        "cp.async.bulk.tensor.2d.shared::cta.global.tile.mbarrier::complete_tx::bytes "
        "[%0], [%1, {%2, %3}], [%4];"
        :: "r"(dst), "l"(tm), "r"(x), "r"(y), "r"(mbar) : "memory");
}
__device__ __forceinline__ void mma16816(float d[4], const uint32_t a[4], uint32_t b0, uint32_t b1) {
    asm volatile(
        "mma.sync.aligned.m16n8k16.row.col.f32.f16.f16.f32 "
        "{%0,%1,%2,%3}, {%4,%5,%6,%7}, {%8,%9}, {%0,%1,%2,%3};\n"
        : "+f"(d[0]), "+f"(d[1]), "+f"(d[2]), "+f"(d[3])
        : "r"(a[0]), "r"(a[1]), "r"(a[2]), "r"(a[3]), "r"(b0), "r"(b1));
}
__device__ __forceinline__ void ldsm4(uint32_t f[4], uint32_t addr) {
    asm volatile("ldmatrix.sync.aligned.m8n8.x4.shared.b16 {%0,%1,%2,%3}, [%4];\n"
                 : "=r"(f[0]), "=r"(f[1]), "=r"(f[2]), "=r"(f[3]) : "r"(addr));
}

// ---------------------------------------------------------------------------
// Merged prep kernel — reductions FIRST, streaming work behind them
// ---------------------------------------------------------------------------
__global__ void prep_all(const float* __restrict__ s, const float* __restrict__ W,
                         const float* __restrict__ b_even, const float* __restrict__ b_odd) {
    const int b = blockIdx.x;
    const int tid = threadIdx.x;
    if (b < PREP_CS2) {
        // csum2[n] = 0.5*rowsum(W[n,:]) + b_even[n]
        __shared__ float red[256];
        int n = b;
        float p = 0.f;
        for (int k = tid; k < SO; k += 256) p += W[(size_t)n * SO + k];
        red[tid] = p;
        __syncthreads();
        for (int st = 128; st > 0; st >>= 1) {
            if (tid < st) red[tid] += red[tid + st];
            __syncthreads();
        }
        if (tid == 0) g_csum2[n] = 0.5f * red[0] + b_even[n];
    } else if (b < PREP_CS2 + PREP_CS1) {
        // csum1[c] = 0.5*colsum(W[:,c]) + b_odd[c]; 64 blocks x (32 cols, 8 k-slices)
        __shared__ float red[8][32];
        int i  = b - PREP_CS2;
        int c  = i * 32 + (tid & 31);
        int ks = tid >> 5;               // 0..7
        float p = 0.f;
        for (int k = ks * 256; k < ks * 256 + 256; k++) p += W[(size_t)k * SO + c];
        red[ks][tid & 31] = p;
        __syncthreads();
        if (tid < 32) {
            float sum = red[0][tid];
#pragma unroll
            for (int j = 1; j < 8; j++) sum += red[j][tid];
            g_csum1[c] = 0.5f * sum + b_odd[c];
        }
    } else if (b < PREP_CS2 + PREP_CS1 + PREP_A) {
        // prepA: rho(s_even)-0.5 -> g_A1 (fp16)
        int id = (b - PREP_CS2 - PREP_CS1) * 256 + tid;
        int m  = id >> 9;
        int kc = id & 511;
        float4 x = reinterpret_cast<const float4*>(s + (size_t)m * (SE + SO))[kc];
        float r0 = rho_f(x.x) - 0.5f;
        float r1 = rho_f(x.y) - 0.5f;
        float r2 = rho_f(x.z) - 0.5f;
        float r3 = rho_f(x.w) - 0.5f;
        __half2* dst = reinterpret_cast<__half2*>(g_A1 + (size_t)m * SE);
        dst[kc * 2 + 0] = __floats2half2_rn(r0, r1);
        dst[kc * 2 + 1] = __floats2half2_rn(r2, r3);
    } else {
        // prepW: W -> g_W2 (fp16) and transpose -> g_W1
        __shared__ float tile[32][33];
        int i  = b - PREP_CS2 - PREP_CS1 - PREP_A;
        int bx = (i & 63) * 32;   // n
        int by = (i >> 6) * 32;   // k
        int tx = tid & 31, ty = tid >> 5;   // 32 x 8
#pragma unroll
        for (int j = 0; j < 32; j += 8) {
            int r = by + ty + j, c = bx + tx;
            float w = W[(size_t)r * SO + c];
            g_W2[(size_t)r * SO + c] = __float2half(w);
            tile[ty + j][tx] = w;
        }
        __syncthreads();
#pragma unroll
        for (int j = 0; j < 32; j += 8) {
            float w = tile[tx][ty + j];
            g_W1[(size_t)(bx + ty + j) * SE + by + tx] = __float2half(w);
        }
    }
}

// ---------------------------------------------------------------------------
// Fused GEMM (TMA + HMMA, deferred-refill producer) + all-tanh iteration
// ---------------------------------------------------------------------------
template <int PHASE>
__global__ void __launch_bounds__(256, 2)
gemm_fused(const __grid_constant__ CUtensorMap tmA,
           const __grid_constant__ CUtensorMap tmB,
           const float* __restrict__ s_in, const float* __restrict__ Ux,
           float* __restrict__ out) {
    extern __shared__ char smem[];
    const uint32_t s0 = cvta_smem(smem);
    const float* csum_g = (PHASE == 1) ? g_csum1 : g_csum2;

    const int tid  = threadIdx.x;
    const int warp = tid >> 5, lane = tid & 31;
    const int wm = warp & 1, wn = warp >> 1;     // 2 warps along M, 4 along N
    const int m0 = blockIdx.y * BM;

    // heavy/light alternation by row parity: co-resident CTAs get mixed
    // durations so epilogue MUFU bursts overlap the other CTA's mainloop.
    const int x = blockIdx.x, y = blockIdx.y;
    int xr;
    if (PHASE == 1) xr = ((y & 1) == 0) ? ((x < 8) ? x + 8 : x - 8) : x;
    else            xr = ((y & 1) == 0) ? x : ((x + 8) & 15);
    const int n0 = xr * BN;

    // block-sparse K range
    int k_lo, k_hi;
    if (PHASE == 1) { k_lo = 0; k_hi = (n0 < H1) ? 1024 : 2048; }
    else            { k_lo = (n0 < H1) ? 0 : 1024; k_hi = 2048; }
    const int total = (k_hi - k_lo) >> 6;        // 16 or 32 k-tiles, >= STG

    const uint32_t fullb = s0;                   // STG x 8 B (TMA tx barriers)
    const uint32_t consb = s0 + 64;              // STG x 8 B (consumed, 8 warp arrivals)
    float* csm = reinterpret_cast<float*>(smem + 256);   // 128 floats in header
    const uint32_t tbase = s0 + 1024;

    if (tid == 0) {
#pragma unroll
        for (int i = 0; i < STG; i++) {
            mbar_init(fullb + 8 * i, 1);
            mbar_init(consb + 8 * i, 8);
        }
    }
    // csum has no GEMM dependency: stage it before the mainloop
    if (tid < BN) csm[tid] = csum_g[n0 + tid];
    __syncthreads();

    auto issue_stage = [&](int st) {
        const int b = st % STG;
        const uint32_t mb = fullb + 8 * b;
        const int kt = k_lo + st * BK;
        const uint32_t d = tbase + b * STAGE_BYTES;
        mbar_expect_tx(mb, STAGE_BYTES);
        tma2d(d,         &tmA, kt, m0, mb);
        tma2d(d + ATILE, &tmB, kt, n0, mb);
    };

    if (tid == 0) {
#pragma unroll
        for (int st = 0; st < STG; st++) issue_stage(st);
    }

    // loop-invariant ldmatrix address components
    const uint32_t arow = wm * 64 + (lane & 15);
    const uint32_t abit = (lane >> 4);
    const uint32_t brow = wn * 32 + ((lane >> 4) << 3) + (lane & 7);
    const uint32_t bbit = ((lane >> 3) & 1);

    float acc[4][4][4];
#pragma unroll
    for (int a = 0; a < 4; a++)
#pragma unroll
        for (int b = 0; b < 4; b++)
#pragma unroll
            for (int c = 0; c < 4; c++) acc[a][b][c] = 0.f;

    for (int st = 0; st < total; st++) {
        const int buf = st % STG;
        const uint32_t ph = (st / STG) & 1;

        // deferred refill: previous tile's buffer, whose consumers had a full
        // extra tile to arrive -> near-zero wait for warp 0
        if (tid == 0 && st > 0 && (st - 1) + STG < total) {
            const int pb = (st - 1) % STG;
            mbar_wait(consb + 8 * pb, ((st - 1) / STG) & 1);
            issue_stage(st - 1 + STG);
        }

        mbar_wait(fullb + 8 * buf, ph);

        const uint32_t bufA = tbase + buf * STAGE_BYTES;
        const uint32_t bufB = bufA + ATILE;

        uint32_t af[2][4][4];
        uint32_t bf[2][2][4];

        auto ldfrags = [&](int ks, int slot) {
#pragma unroll
            for (int mi = 0; mi < 4; mi++) {
                uint32_t row = arow + mi * 16;
                uint32_t chunk = (ks * 2 + abit) ^ (row & 7);
                ldsm4(af[slot][mi], bufA + row * 128 + (chunk << 4));
            }
#pragma unroll
            for (int nj = 0; nj < 2; nj++) {
                uint32_t row = brow + nj * 16;
                uint32_t chunk = (ks * 2 + bbit) ^ (row & 7);
                ldsm4(bf[slot][nj], bufB + row * 128 + (chunk << 4));
            }
        };

        ldfrags(0, 0);
#pragma unroll
        for (int ks = 0; ks < 4; ks++) {
            const int cur = ks & 1;
            if (ks < 3) ldfrags(ks + 1, cur ^ 1);
#pragma unroll
            for (int mi = 0; mi < 4; mi++)
#pragma unroll
                for (int ni = 0; ni < 4; ni++)
                    mma16816(acc[mi][ni], af[cur][mi],
                             bf[cur][ni >> 1][(ni & 1) * 2],
                             bf[cur][ni >> 1][(ni & 1) * 2 + 1]);
        }

        // mark this buffer consumed (only needed if it will be refilled)
        if (lane == 0 && st + STG < total) mbar_arrive(consb + 8 * buf);
    }

    // ---------------- fused epilogue (all-tanh), per-warp immediate entry ----
    // No block sync needed: each warp consumes only its own acc + read-only csm
    // (csm was staged and synced before the mainloop).
    const int g  = lane >> 2;
    const int i2 = (lane & 3) * 2;
    const int col_off = (PHASE == 1) ? SO : 0;
    const bool tile_has_ux = (PHASE == 1) && (n0 < H1);

#pragma unroll
    for (int mi = 0; mi < 4; mi++) {
#pragma unroll
        for (int rr = 0; rr < 2; rr++) {
            const int row = m0 + wm * 64 + mi * 16 + g + rr * 8;
#pragma unroll
            for (int ni = 0; ni < 4; ni++) {
                const int lc  = wn * 32 + ni * 8 + i2;     // local col pair
                const int col = n0 + lc;
                float c0 = acc[mi][ni][rr * 2 + 0] + csm[lc + 0];
                float c1 = acc[mi][ni][rr * 2 + 1] + csm[lc + 1];
                if (tile_has_ux) {
                    float2 u = *reinterpret_cast<const float2*>(Ux + (size_t)row * H1 + col);
                    c0 += u.x; c1 += u.y;
                }
                float2 sv = *reinterpret_cast<const float2*>(
                    s_in + (size_t)row * (SE + SO) + col_off + col);
                const float h0 = 0.5f * c0, h1 = 0.5f * c1;
#pragma unroll
                for (int it = 0; it < NSTEP; it++) {
                    float t0 = tanh_ap(fmaf(2.0f, sv.x, -1.0f));
                    float t1 = tanh_ap(fmaf(2.0f, sv.y, -1.0f));
                    sv.x = fmaf(-h0 * t0, t0, fmaf(0.5f, sv.x, h0));
                    sv.y = fmaf(-h1 * t1, t1, fmaf(0.5f, sv.y, h1));
                }
                *reinterpret_cast<float2*>(out + (size_t)row * (SE + SO) + col_off + col) = sv;
                if (PHASE == 1) {
                    // rho(s)-0.5 = 0.5*tanh(2s-1)
                    float r0 = 0.5f * tanh_ap(fmaf(2.0f, sv.x, -1.0f));
                    float r1 = 0.5f * tanh_ap(fmaf(2.0f, sv.y, -1.0f));
                    *reinterpret_cast<__half2*>(g_A2 + (size_t)row * SE + col) =
                        __floats2half2_rn(r0, r1);
                }
            }
        }
    }
}

// ---------------------------------------------------------------------------
// Host: tensor-map encoding via driver entry point (no -lcuda needed)
// ---------------------------------------------------------------------------
typedef CUresult (*encode_fn_t)(CUtensorMap*, CUtensorMapDataType, cuuint32_t, void*,
                                const cuuint64_t*, const cuuint64_t*, const cuuint32_t*,
                                const cuuint32_t*, CUtensorMapInterleave, CUtensorMapSwizzle,
                                CUtensorMapL2promotion, CUtensorMapFloatOOBfill);

static void encode_tm(encode_fn_t enc, CUtensorMap* tm, void* base,
                      unsigned long long rows) {
    cuuint64_t gd[2] = {2048ull, rows};
    cuuint64_t gs[1] = {4096ull};          // row stride in bytes
    cuuint32_t box[2] = {64u, 128u};       // K box (128 B) x 128 rows
    cuuint32_t es[2] = {1u, 1u};
    enc(tm, CU_TENSOR_MAP_DATA_TYPE_FLOAT16, 2, base, gd, gs, box, es,
        CU_TENSOR_MAP_INTERLEAVE_NONE, CU_TENSOR_MAP_SWIZZLE_128B,
        CU_TENSOR_MAP_L2_PROMOTION_L2_128B, CU_TENSOR_MAP_FLOAT_OOB_FILL_NONE);
}

extern "C" void kernel_launch(void* const* d_in, const int* in_sizes, int n_in,
                              void* d_out, int out_size) {
    const float* Ux     = (const float*)d_in[0];
    const float* s      = (const float*)d_in[1];
    const float* W      = (const float*)d_in[2];
    const float* b_even = (const float*)d_in[3];
    const float* b_odd  = (const float*)d_in[4];
    float* out = (float*)d_out;

    encode_fn_t enc = nullptr;
    cudaDriverEntryPointQueryResult qr;
    cudaGetDriverEntryPoint("cuTensorMapEncodeTiled", (void**)&enc, cudaEnableDefault, &qr);

    void *pA1, *pA2, *pW1, *pW2;
    cudaGetSymbolAddress(&pA1, g_A1);
    cudaGetSymbolAddress(&pA2, g_A2);
    cudaGetSymbolAddress(&pW1, g_W1);
    cudaGetSymbolAddress(&pW2, g_W2);

    CUtensorMap tmA1, tmA2, tmW1, tmW2;
    encode_tm(enc, &tmA1, pA1, BSZ);
    encode_tm(enc, &tmA2, pA2, BSZ);
    encode_tm(enc, &tmW1, pW1, SO);
    encode_tm(enc, &tmW2, pW2, SE);

    cudaFuncSetAttribute(gemm_fused<1>, cudaFuncAttributeMaxDynamicSharedMemorySize, SMEM_ALLOC);
    cudaFuncSetAttribute(gemm_fused<2>, cudaFuncAttributeMaxDynamicSharedMemorySize, SMEM_ALLOC);

    prep_all<<<PREP_GRID, 256>>>(s, W, b_even, b_odd);

    dim3 grid(SO / BN, BSZ / BM);   // (16, 128)
    gemm_fused<1><<<grid, 256, SMEM_ALLOC>>>(tmA1, tmW1, s, Ux, out);
    gemm_fused<2><<<grid, 256, SMEM_ALLOC>>>(tmA2, tmW2, s, Ux, out);
}